// round 1
// baseline (speedup 1.0000x reference)
#include <cuda_runtime.h>

#define Bb 4
#define Nn 8192
#define Ss 2048
#define C1c 128
#define C2c 256
#define CIN 384
#define Hh 256
#define Pp (Bb*Nn)      // 32768
#define PT 256          // P tiles of 128 -> gridDim.x for gemm

// ------------------- scratch (device globals; no allocation) -------------------
__device__ float g_pts2t[Bb*Ss*C2c];        // [B][S][C2]   8 MB
__device__ float g_feat[(size_t)Pp*CIN];    // [P][384]    50 MB
__device__ float g_y1[(size_t)Pp*Hh];       // [P][256]    32 MB
__device__ float g_y2[(size_t)Pp*Hh];       // [P][256]    32 MB
__device__ float g_partS[2][Hh][PT];
__device__ float g_partQ[2][Hh][PT];
__device__ float g_scale[2][Hh];
__device__ float g_shift[2][Hh];

// ------------------- transpose [B][C][N] -> rows (b*N+n), cols c -------------------
// out[(b*Ncol+n)*outStride + outOff + c] = in[b][c][n]
__global__ void transpose_cn(const float* __restrict__ in, int C, int Ncol,
                             int outStride, int outOff, int which /*0: pts2t, 1: feat*/) {
    __shared__ float tile[32][33];
    float* out = (which == 0) ? g_pts2t : g_feat;
    int b = blockIdx.z;
    int n0 = blockIdx.x * 32, c0 = blockIdx.y * 32;
    int tx = threadIdx.x, ty = threadIdx.y;
#pragma unroll
    for (int k = 0; k < 4; k++) {
        int c = c0 + ty + k * 8;
        tile[ty + k * 8][tx] = in[((size_t)b * C + c) * Ncol + n0 + tx];
    }
    __syncthreads();
#pragma unroll
    for (int k = 0; k < 4; k++) {
        int n = n0 + ty + k * 8;
        out[((size_t)b * Ncol + n) * outStride + outOff + c0 + tx] = tile[tx][ty + k * 8];
    }
}

// ------------------- kNN(3) + inverse-distance interpolation -------------------
// one warp handles 8 queries; CTA (256 thr) handles 64 queries of one batch
__global__ void knn_interp(const float* __restrict__ xyz1, const float* __restrict__ xyz2) {
    __shared__ float xs[Ss], ys[Ss], zs[Ss];
    int b = blockIdx.y;
    int n_base = blockIdx.x * 64;

    const float* x2 = xyz2 + (size_t)b * Ss * 3;
    for (int i = threadIdx.x; i < Ss * 3; i += blockDim.x) {
        float v = x2[i];
        int s = i / 3, c = i - s * 3;
        if (c == 0) xs[s] = v; else if (c == 1) ys[s] = v; else zs[s] = v;
    }
    __syncthreads();

    int warp = threadIdx.x >> 5, lane = threadIdx.x & 31;
    for (int q = 0; q < 8; q++) {
        int n = n_base + warp * 8 + q;
        const float* xq = xyz1 + ((size_t)b * Nn + n) * 3;
        float qx = xq[0], qy = xq[1], qz = xq[2];

        float d0 = 3.4e38f, d1 = 3.4e38f, d2 = 3.4e38f;
        int i0 = 0x7fffffff, i1 = 0x7fffffff, i2 = 0x7fffffff;
        for (int s = lane; s < Ss; s += 32) {
            float dx = xs[s] - qx, dy = ys[s] - qy, dz = zs[s] - qz;
            float d = fmaf(dx, dx, fmaf(dy, dy, dz * dz));
            if (d < d2) {
                if (d < d1) {
                    d2 = d1; i2 = i1;
                    if (d < d0) { d1 = d0; i1 = i0; d0 = d; i0 = s; }
                    else        { d1 = d;  i1 = s; }
                } else { d2 = d; i2 = s; }
            }
        }
        // warp-merge the 3 global minima from per-lane sorted top-3 lists
        float bd[3]; int bi[3];
        float h = d0; int hi = i0; int slot = 0;
        for (int k = 0; k < 3; k++) {
            float v = h; int vi = hi;
#pragma unroll
            for (int off = 16; off; off >>= 1) {
                float ov = __shfl_xor_sync(0xffffffffu, v, off);
                int   oi = __shfl_xor_sync(0xffffffffu, vi, off);
                if (ov < v || (ov == v && oi < vi)) { v = ov; vi = oi; }
            }
            bd[k] = v; bi[k] = vi;
            if (h == v && hi == vi) { slot++; h = (slot == 1) ? d1 : d2; hi = (slot == 1) ? i1 : i2; }
        }
        float r0 = 1.f / (bd[0] + 1e-8f);
        float r1 = 1.f / (bd[1] + 1e-8f);
        float r2 = 1.f / (bd[2] + 1e-8f);
        float inv = 1.f / (r0 + r1 + r2);
        float w0 = r0 * inv, w1 = r1 * inv, w2 = r2 * inv;

        const float* p0 = g_pts2t + ((size_t)b * Ss + bi[0]) * C2c;
        const float* p1 = g_pts2t + ((size_t)b * Ss + bi[1]) * C2c;
        const float* p2 = g_pts2t + ((size_t)b * Ss + bi[2]) * C2c;
        float* f = g_feat + ((size_t)b * Nn + n) * CIN + C1c;
#pragma unroll
        for (int j = 0; j < 8; j++) {
            int c = lane + 32 * j;
            f[c] = w0 * p0[c] + w1 * p1[c] + w2 * p2[c];
        }
    }
}

// ------------------- GEMM: C[P][256] = A[P][K] * W[256][K]^T (+bias), BN-partials ----
// LAYER 0: A=g_feat -> C=g_y1 ; LAYER 1: A=relu(bn1(g_y1)) -> C=g_y2
template <int K, bool APPLY_BN, int LAYER>
__global__ void gemm_bn(const float* __restrict__ W, const float* __restrict__ bias) {
    __shared__ float As[16][128];
    __shared__ float Bs[16][128];
    __shared__ float redS[16][128];
    __shared__ float redQ[16][128];

    const float* A = (LAYER == 0) ? g_feat : g_y1;
    float* C       = (LAYER == 0) ? g_y1   : g_y2;
    const float* scale = g_scale[0];
    const float* shift = g_shift[0];

    int tid = threadIdx.x;
    int gx = blockIdx.x, gy = blockIdx.y;
    int p0 = gx * 128, m0 = gy * 128;
    int tx = tid & 15, ty = tid >> 4;
    int lr = tid >> 2;          // 0..63
    int lc = (tid & 3) * 4;     // 0,4,8,12

    float acc[8][8];
#pragma unroll
    for (int i = 0; i < 8; i++)
#pragma unroll
        for (int j = 0; j < 8; j++) acc[i][j] = 0.f;

    for (int kt = 0; kt < K; kt += 16) {
#pragma unroll
        for (int h = 0; h < 2; h++) {
            int row = lr + h * 64;
            float4 v = *(const float4*)&A[(size_t)(p0 + row) * K + kt + lc];
            if (APPLY_BN) {
                v.x = fmaxf(fmaf(v.x, scale[kt + lc + 0], shift[kt + lc + 0]), 0.f);
                v.y = fmaxf(fmaf(v.y, scale[kt + lc + 1], shift[kt + lc + 1]), 0.f);
                v.z = fmaxf(fmaf(v.z, scale[kt + lc + 2], shift[kt + lc + 2]), 0.f);
                v.w = fmaxf(fmaf(v.w, scale[kt + lc + 3], shift[kt + lc + 3]), 0.f);
            }
            As[lc + 0][row] = v.x; As[lc + 1][row] = v.y;
            As[lc + 2][row] = v.z; As[lc + 3][row] = v.w;
            float4 w = *(const float4*)&W[(size_t)(m0 + row) * K + kt + lc];
            Bs[lc + 0][row] = w.x; Bs[lc + 1][row] = w.y;
            Bs[lc + 2][row] = w.z; Bs[lc + 3][row] = w.w;
        }
        __syncthreads();
#pragma unroll
        for (int kk = 0; kk < 16; kk++) {
            float a[8], bb[8];
            *(float4*)&a[0]  = *(const float4*)&As[kk][ty * 4];
            *(float4*)&a[4]  = *(const float4*)&As[kk][64 + ty * 4];
            *(float4*)&bb[0] = *(const float4*)&Bs[kk][tx * 4];
            *(float4*)&bb[4] = *(const float4*)&Bs[kk][64 + tx * 4];
#pragma unroll
            for (int i = 0; i < 8; i++)
#pragma unroll
                for (int j = 0; j < 8; j++)
                    acc[i][j] = fmaf(a[i], bb[j], acc[i][j]);
        }
        __syncthreads();
    }

    int mc[8], pr[8];
#pragma unroll
    for (int j = 0; j < 4; j++) { mc[j] = tx * 4 + j; mc[j + 4] = 64 + tx * 4 + j; }
#pragma unroll
    for (int i = 0; i < 4; i++) { pr[i] = ty * 4 + i; pr[i + 4] = 64 + ty * 4 + i; }

    float bj[8];
#pragma unroll
    for (int j = 0; j < 8; j++) bj[j] = bias[m0 + mc[j]];
#pragma unroll
    for (int i = 0; i < 8; i++)
#pragma unroll
        for (int j = 0; j < 8; j++) acc[i][j] += bj[j];

    // write C (point-major [P][256])
#pragma unroll
    for (int i = 0; i < 8; i++) {
        float4 v0 = make_float4(acc[i][0], acc[i][1], acc[i][2], acc[i][3]);
        float4 v1 = make_float4(acc[i][4], acc[i][5], acc[i][6], acc[i][7]);
        size_t base = (size_t)(p0 + pr[i]) * Hh + m0;
        *(float4*)&C[base + tx * 4]      = v0;
        *(float4*)&C[base + 64 + tx * 4] = v1;
    }

    // per-CTA BN partial sums (deterministic; no atomics)
    float s[8], q[8];
#pragma unroll
    for (int j = 0; j < 8; j++) {
        s[j] = 0.f; q[j] = 0.f;
#pragma unroll
        for (int i = 0; i < 8; i++) { s[j] += acc[i][j]; q[j] += acc[i][j] * acc[i][j]; }
    }
#pragma unroll
    for (int j = 0; j < 8; j++) { redS[ty][mc[j]] = s[j]; redQ[ty][mc[j]] = q[j]; }
    __syncthreads();
    if (tid < 128) {
        float ss = 0.f, qq = 0.f;
#pragma unroll
        for (int r = 0; r < 16; r++) { ss += redS[r][tid]; qq += redQ[r][tid]; }
        g_partS[LAYER][m0 + tid][gx] = ss;
        g_partQ[LAYER][m0 + tid][gx] = qq;
    }
}

// ------------------- BN stats -> per-channel scale/shift -------------------
template <int LAYER>
__global__ void bnstats(const float* __restrict__ gamma, const float* __restrict__ beta) {
    int m = threadIdx.x;
    float s = 0.f, q = 0.f;
#pragma unroll 8
    for (int i = 0; i < PT; i++) { s += g_partS[LAYER][m][i]; q += g_partQ[LAYER][m][i]; }
    const float invP = 1.f / (float)Pp;
    float mean = s * invP;
    float var = q * invP - mean * mean;
    float sc = gamma[m] * rsqrtf(var + 1e-5f);
    g_scale[LAYER][m] = sc;
    g_shift[LAYER][m] = beta[m] - mean * sc;
}

// ------------------- final: relu(bn2(y2)) -> out [B][256][N] (transpose) -------------
__global__ void bn_out(float* __restrict__ out) {
    __shared__ float tile[32][33];
    int b = blockIdx.z;
    int n0 = blockIdx.x * 32, m0 = blockIdx.y * 32;
    int tx = threadIdx.x, ty = threadIdx.y;
#pragma unroll
    for (int k = 0; k < 4; k++) {
        int nn = ty + k * 8;
        tile[nn][tx] = g_y2[((size_t)b * Nn + n0 + nn) * Hh + m0 + tx];
    }
    __syncthreads();
#pragma unroll
    for (int k = 0; k < 4; k++) {
        int m = m0 + ty + k * 8;
        float v = fmaxf(fmaf(tile[tx][ty + k * 8], g_scale[1][m], g_shift[1][m]), 0.f);
        out[(size_t)b * Hh * Nn + (size_t)m * Nn + n0 + tx] = v;
    }
}

// ------------------- launch -------------------
extern "C" void kernel_launch(void* const* d_in, const int* in_sizes, int n_in,
                              void* d_out, int out_size) {
    const float* xyz1    = (const float*)d_in[0];   // [B,N,3]
    const float* xyz2    = (const float*)d_in[1];   // [B,S,3]
    const float* points1 = (const float*)d_in[2];   // [B,C1,N]
    const float* points2 = (const float*)d_in[3];   // [B,C2,S]
    const float* W1      = (const float*)d_in[4];   // [H1,CIN]
    const float* b1      = (const float*)d_in[5];
    const float* gamma1  = (const float*)d_in[6];
    const float* beta1   = (const float*)d_in[7];
    const float* W2      = (const float*)d_in[8];   // [H2,H1]
    const float* b2      = (const float*)d_in[9];
    const float* gamma2  = (const float*)d_in[10];
    const float* beta2   = (const float*)d_in[11];
    float* out = (float*)d_out;                     // [B,256,N]

    dim3 tb(32, 8);
    // points2 [B,256,S] -> g_pts2t [B,S,256]
    transpose_cn<<<dim3(Ss / 32, C2c / 32, Bb), tb>>>(points2, C2c, Ss, C2c, 0, 0);
    // points1 [B,128,N] -> g_feat[:, 0:128]
    transpose_cn<<<dim3(Nn / 32, C1c / 32, Bb), tb>>>(points1, C1c, Nn, CIN, 0, 1);
    // kNN + interp -> g_feat[:, 128:384]
    knn_interp<<<dim3(Nn / 64, Bb), 256>>>(xyz1, xyz2);
    // layer 1
    gemm_bn<CIN, false, 0><<<dim3(PT, 2), 256>>>(W1, b1);
    bnstats<0><<<1, 256>>>(gamma1, beta1);
    // layer 2 (BN1+ReLU fused into A-load)
    gemm_bn<Hh, true, 1><<<dim3(PT, 2), 256>>>(W2, b2);
    bnstats<1><<<1, 256>>>(gamma2, beta2);
    // BN2+ReLU + transpose to [B,256,N]
    bn_out<<<dim3(Nn / 32, Hh / 32, Bb), tb>>>(out);
    (void)in_sizes; (void)n_in; (void)out_size;
}

// round 2
// speedup vs baseline: 1.0656x; 1.0656x over previous
#include <cuda_runtime.h>

#define Bb 4
#define Nn 8192
#define Ss 2048
#define C1c 128
#define C2c 256
#define CIN 384
#define Hh 256
#define Pp (Bb*Nn)      // 32768
#define PT 256          // P tiles of 128

// ------------------- scratch (device globals; no allocation) -------------------
__device__ float g_pts2t[Bb*Ss*C2c];        // [B][S][C2]
__device__ float g_feat[(size_t)Pp*CIN];    // [P][384]
__device__ float g_y1[(size_t)Pp*Hh];       // [P][256]
__device__ float g_y2[(size_t)Pp*Hh];       // [P][256]
__device__ float g_partS[2][Hh][PT];
__device__ float g_partQ[2][Hh][PT];
__device__ float g_scale[2][Hh];
__device__ float g_shift[2][Hh];

// packed fp32x2 FMA (Blackwell FFMA2 — only reachable via PTX)
__device__ __forceinline__ float2 ffma2(float2 a, float2 b, float2 c) {
    float2 d;
    asm("fma.rn.f32x2 %0, %1, %2, %3;"
        : "=l"(reinterpret_cast<unsigned long long&>(d))
        : "l"(reinterpret_cast<unsigned long long&>(a)),
          "l"(reinterpret_cast<unsigned long long&>(b)),
          "l"(reinterpret_cast<unsigned long long&>(c)));
    return d;
}

// ------------------- transpose [B][C][N] -> rows (b*N+n), cols c -------------------
__global__ void transpose_cn(const float* __restrict__ in, int C, int Ncol,
                             int outStride, int outOff, int which) {
    __shared__ float tile[32][33];
    float* out = (which == 0) ? g_pts2t : g_feat;
    int b = blockIdx.z;
    int n0 = blockIdx.x * 32, c0 = blockIdx.y * 32;
    int tx = threadIdx.x, ty = threadIdx.y;
#pragma unroll
    for (int k = 0; k < 4; k++) {
        int c = c0 + ty + k * 8;
        tile[ty + k * 8][tx] = in[((size_t)b * C + c) * Ncol + n0 + tx];
    }
    __syncthreads();
#pragma unroll
    for (int k = 0; k < 4; k++) {
        int n = n0 + ty + k * 8;
        out[((size_t)b * Ncol + n) * outStride + outOff + c0 + tx] = tile[tx][ty + k * 8];
    }
}

// ------------------- kNN(3) + inverse-distance interpolation -------------------
// candidates staged as float4(x,y,z,|x|^2); compare on e = |x|^2 - 2 q.x
__global__ void knn_interp(const float* __restrict__ xyz1, const float* __restrict__ xyz2) {
    __shared__ float4 c4[Ss];
    int b = blockIdx.y;
    int n_base = blockIdx.x * 64;

    const float* x2 = xyz2 + (size_t)b * Ss * 3;
    for (int s = threadIdx.x; s < Ss; s += blockDim.x) {
        float x = x2[s * 3 + 0], y = x2[s * 3 + 1], z = x2[s * 3 + 2];
        c4[s] = make_float4(x, y, z, fmaf(x, x, fmaf(y, y, z * z)));
    }
    __syncthreads();

    int warp = threadIdx.x >> 5, lane = threadIdx.x & 31;
    for (int q = 0; q < 8; q++) {
        int n = n_base + warp * 8 + q;
        const float* xq = xyz1 + ((size_t)b * Nn + n) * 3;
        float qx = xq[0], qy = xq[1], qz = xq[2];
        float qsq = fmaf(qx, qx, fmaf(qy, qy, qz * qz));

        float e0 = 3.4e38f, e1 = 3.4e38f, e2 = 3.4e38f;
        int i0 = 0x7fffffff, i1 = 0x7fffffff, i2 = 0x7fffffff;
#pragma unroll 4
        for (int s = lane; s < Ss; s += 32) {
            float4 c = c4[s];
            float dot = fmaf(qx, c.x, fmaf(qy, c.y, qz * c.z));
            float e = fmaf(-2.0f, dot, c.w);
            if (e < e2) {
                if (e < e1) {
                    e2 = e1; i2 = i1;
                    if (e < e0) { e1 = e0; i1 = i0; e0 = e; i0 = s; }
                    else        { e1 = e;  i1 = s; }
                } else { e2 = e; i2 = s; }
            }
        }
        // warp-merge global top-3 from per-lane sorted lists
        float be[3]; int bi[3];
        float h = e0; int hi = i0; int slot = 0;
        for (int k = 0; k < 3; k++) {
            float v = h; int vi = hi;
#pragma unroll
            for (int off = 16; off; off >>= 1) {
                float ov = __shfl_xor_sync(0xffffffffu, v, off);
                int   oi = __shfl_xor_sync(0xffffffffu, vi, off);
                if (ov < v || (ov == v && oi < vi)) { v = ov; vi = oi; }
            }
            be[k] = v; bi[k] = vi;
            if (h == v && hi == vi) { slot++; h = (slot == 1) ? e1 : e2; hi = (slot == 1) ? i1 : i2; }
        }
        float d0 = fmaxf(be[0] + qsq, 0.f);
        float d1 = fmaxf(be[1] + qsq, 0.f);
        float d2 = fmaxf(be[2] + qsq, 0.f);
        float r0 = 1.f / (d0 + 1e-8f);
        float r1 = 1.f / (d1 + 1e-8f);
        float r2 = 1.f / (d2 + 1e-8f);
        float inv = 1.f / (r0 + r1 + r2);
        float w0 = r0 * inv, w1 = r1 * inv, w2 = r2 * inv;

        const float* p0 = g_pts2t + ((size_t)b * Ss + bi[0]) * C2c;
        const float* p1 = g_pts2t + ((size_t)b * Ss + bi[1]) * C2c;
        const float* p2 = g_pts2t + ((size_t)b * Ss + bi[2]) * C2c;
        float* f = g_feat + ((size_t)b * Nn + n) * CIN + C1c;
#pragma unroll
        for (int j = 0; j < 8; j++) {
            int c = lane + 32 * j;
            f[c] = w0 * p0[c] + w1 * p1[c] + w2 * p2[c];
        }
    }
}

// ------------------- GEMM: C[P][256] = A[P][K] * W[256][K]^T (+bias), BN-partials ----
template <int K, bool APPLY_BN, int LAYER>
__global__ void __launch_bounds__(256, 2) gemm_bn(const float* __restrict__ W,
                                                  const float* __restrict__ bias) {
    __shared__ float As[16][128];
    __shared__ float Bs[16][128];
    // reduction buffers alias As/Bs (dead after mainloop)
    float (*redS)[128] = As;
    float (*redQ)[128] = Bs;

    const float* A = (LAYER == 0) ? g_feat : g_y1;
    float* C       = (LAYER == 0) ? g_y1   : g_y2;
    const float* scale = g_scale[0];
    const float* shift = g_shift[0];

    int tid = threadIdx.x;
    int gx = blockIdx.x, gy = blockIdx.y;
    int p0 = gx * 128, m0 = gy * 128;
    int tx = tid & 15, ty = tid >> 4;
    int lr = tid >> 2;          // 0..63
    int lc = (tid & 3) * 4;     // 0,4,8,12

    float2 acc[8][4];
#pragma unroll
    for (int i = 0; i < 8; i++)
#pragma unroll
        for (int j = 0; j < 4; j++) acc[i][j] = make_float2(0.f, 0.f);

    for (int kt = 0; kt < K; kt += 16) {
#pragma unroll
        for (int h = 0; h < 2; h++) {
            int row = lr + h * 64;
            float4 v = *(const float4*)&A[(size_t)(p0 + row) * K + kt + lc];
            if (APPLY_BN) {
                v.x = fmaxf(fmaf(v.x, scale[kt + lc + 0], shift[kt + lc + 0]), 0.f);
                v.y = fmaxf(fmaf(v.y, scale[kt + lc + 1], shift[kt + lc + 1]), 0.f);
                v.z = fmaxf(fmaf(v.z, scale[kt + lc + 2], shift[kt + lc + 2]), 0.f);
                v.w = fmaxf(fmaf(v.w, scale[kt + lc + 3], shift[kt + lc + 3]), 0.f);
            }
            As[lc + 0][row] = v.x; As[lc + 1][row] = v.y;
            As[lc + 2][row] = v.z; As[lc + 3][row] = v.w;
            float4 w = *(const float4*)&W[(size_t)(m0 + row) * K + kt + lc];
            Bs[lc + 0][row] = w.x; Bs[lc + 1][row] = w.y;
            Bs[lc + 2][row] = w.z; Bs[lc + 3][row] = w.w;
        }
        __syncthreads();
#pragma unroll
        for (int kk = 0; kk < 16; kk++) {
            const float4* As4 = (const float4*)&As[kk][0];
            const float4* Bs4 = (const float4*)&Bs[kk][0];
            float4 a0 = As4[ty], a1 = As4[16 + ty];
            float4 b0 = Bs4[tx], b1 = Bs4[16 + tx];
            float2 bp[4] = { make_float2(b0.x, b0.y), make_float2(b0.z, b0.w),
                             make_float2(b1.x, b1.y), make_float2(b1.z, b1.w) };
            float2 ad[8] = { make_float2(a0.x, a0.x), make_float2(a0.y, a0.y),
                             make_float2(a0.z, a0.z), make_float2(a0.w, a0.w),
                             make_float2(a1.x, a1.x), make_float2(a1.y, a1.y),
                             make_float2(a1.z, a1.z), make_float2(a1.w, a1.w) };
#pragma unroll
            for (int i = 0; i < 8; i++)
#pragma unroll
                for (int jp = 0; jp < 4; jp++)
                    acc[i][jp] = ffma2(ad[i], bp[jp], acc[i][jp]);
        }
        __syncthreads();
    }

    int mc[8], pr[8];
#pragma unroll
    for (int j = 0; j < 4; j++) { mc[j] = tx * 4 + j; mc[j + 4] = 64 + tx * 4 + j; }
#pragma unroll
    for (int i = 0; i < 4; i++) { pr[i] = ty * 4 + i; pr[i + 4] = 64 + ty * 4 + i; }

    float bj[8];
#pragma unroll
    for (int j = 0; j < 8; j++) bj[j] = bias[m0 + mc[j]];

    float s[8], q[8];
#pragma unroll
    for (int j = 0; j < 8; j++) { s[j] = 0.f; q[j] = 0.f; }

#pragma unroll
    for (int i = 0; i < 8; i++) {
        float row[8];
        row[0] = acc[i][0].x + bj[0]; row[1] = acc[i][0].y + bj[1];
        row[2] = acc[i][1].x + bj[2]; row[3] = acc[i][1].y + bj[3];
        row[4] = acc[i][2].x + bj[4]; row[5] = acc[i][2].y + bj[5];
        row[6] = acc[i][3].x + bj[6]; row[7] = acc[i][3].y + bj[7];
        size_t base = (size_t)(p0 + pr[i]) * Hh + m0;
        *(float4*)&C[base + tx * 4]      = make_float4(row[0], row[1], row[2], row[3]);
        *(float4*)&C[base + 64 + tx * 4] = make_float4(row[4], row[5], row[6], row[7]);
#pragma unroll
        for (int j = 0; j < 8; j++) { s[j] += row[j]; q[j] += row[j] * row[j]; }
    }

    __syncthreads();   // As/Bs reads done; safe to reuse as redS/redQ
#pragma unroll
    for (int j = 0; j < 8; j++) { redS[ty][mc[j]] = s[j]; redQ[ty][mc[j]] = q[j]; }
    __syncthreads();
    if (tid < 128) {
        float ss = 0.f, qq = 0.f;
#pragma unroll
        for (int r = 0; r < 16; r++) { ss += redS[r][tid]; qq += redQ[r][tid]; }
        g_partS[LAYER][m0 + tid][gx] = ss;
        g_partQ[LAYER][m0 + tid][gx] = qq;
    }
}

// ------------------- BN stats -> per-channel scale/shift -------------------
template <int LAYER>
__global__ void bnstats(const float* __restrict__ gamma, const float* __restrict__ beta) {
    int m = threadIdx.x;
    float s = 0.f, q = 0.f;
#pragma unroll 8
    for (int i = 0; i < PT; i++) { s += g_partS[LAYER][m][i]; q += g_partQ[LAYER][m][i]; }
    const float invP = 1.f / (float)Pp;
    float mean = s * invP;
    float var = q * invP - mean * mean;
    float sc = gamma[m] * rsqrtf(var + 1e-5f);
    g_scale[LAYER][m] = sc;
    g_shift[LAYER][m] = beta[m] - mean * sc;
}

// ------------------- final: relu(bn2(y2)) -> out [B][256][N] (transpose) -------------
__global__ void bn_out(float* __restrict__ out) {
    __shared__ float tile[32][33];
    int b = blockIdx.z;
    int n0 = blockIdx.x * 32, m0 = blockIdx.y * 32;
    int tx = threadIdx.x, ty = threadIdx.y;
#pragma unroll
    for (int k = 0; k < 4; k++) {
        int nn = ty + k * 8;
        tile[nn][tx] = g_y2[((size_t)b * Nn + n0 + nn) * Hh + m0 + tx];
    }
    __syncthreads();
#pragma unroll
    for (int k = 0; k < 4; k++) {
        int m = m0 + ty + k * 8;
        float v = fmaxf(fmaf(tile[tx][ty + k * 8], g_scale[1][m], g_shift[1][m]), 0.f);
        out[(size_t)b * Hh * Nn + (size_t)m * Nn + n0 + tx] = v;
    }
}

// ------------------- launch -------------------
extern "C" void kernel_launch(void* const* d_in, const int* in_sizes, int n_in,
                              void* d_out, int out_size) {
    const float* xyz1    = (const float*)d_in[0];
    const float* xyz2    = (const float*)d_in[1];
    const float* points1 = (const float*)d_in[2];
    const float* points2 = (const float*)d_in[3];
    const float* W1      = (const float*)d_in[4];
    const float* b1      = (const float*)d_in[5];
    const float* gamma1  = (const float*)d_in[6];
    const float* beta1   = (const float*)d_in[7];
    const float* W2      = (const float*)d_in[8];
    const float* b2      = (const float*)d_in[9];
    const float* gamma2  = (const float*)d_in[10];
    const float* beta2   = (const float*)d_in[11];
    float* out = (float*)d_out;

    dim3 tb(32, 8);
    transpose_cn<<<dim3(Ss / 32, C2c / 32, Bb), tb>>>(points2, C2c, Ss, C2c, 0, 0);
    transpose_cn<<<dim3(Nn / 32, C1c / 32, Bb), tb>>>(points1, C1c, Nn, CIN, 0, 1);
    knn_interp<<<dim3(Nn / 64, Bb), 256>>>(xyz1, xyz2);
    gemm_bn<CIN, false, 0><<<dim3(PT, 2), 256>>>(W1, b1);
    bnstats<0><<<1, 256>>>(gamma1, beta1);
    gemm_bn<Hh, true, 1><<<dim3(PT, 2), 256>>>(W2, b2);
    bnstats<1><<<1, 256>>>(gamma2, beta2);
    bn_out<<<dim3(Nn / 32, Hh / 32, Bb), tb>>>(out);
    (void)in_sizes; (void)n_in; (void)out_size;
}

// round 9
// speedup vs baseline: 1.1657x; 1.0939x over previous
#include <cuda_runtime.h>
#include <cuda_bf16.h>
#include <cstdint>

#define Bb 4
#define Nn 8192
#define Ss 2048
#define C1c 128
#define C2c 256
#define CIN 384
#define Hh 256
#define Pp (Bb*Nn)      // 32768
#define PT 256          // P tiles of 128

// ------------------- scratch (device globals; no allocation) -------------------
__device__ float g_pts2t[Bb*Ss*C2c];
__device__ __nv_bfloat16 g_featH[(size_t)Pp*CIN];
__device__ __nv_bfloat16 g_featL[(size_t)Pp*CIN];
__device__ float g_y1[(size_t)Pp*Hh];
__device__ __nv_bfloat16 g_y1H[(size_t)Pp*Hh];
__device__ __nv_bfloat16 g_y1L[(size_t)Pp*Hh];
__device__ float g_y2[(size_t)Pp*Hh];
__device__ __nv_bfloat16 g_W1H[Hh*CIN];
__device__ __nv_bfloat16 g_W1L[Hh*CIN];
__device__ __nv_bfloat16 g_W2H[Hh*Hh];
__device__ __nv_bfloat16 g_W2L[Hh*Hh];
__device__ float g_partS[2][Hh][PT];
__device__ float g_partQ[2][Hh][PT];
__device__ float g_scale[2][Hh];
__device__ float g_shift[2][Hh];

__device__ __forceinline__ void bf16split(float v, __nv_bfloat16& h, __nv_bfloat16& l) {
    h = __float2bfloat16(v);
    l = __float2bfloat16(v - __bfloat162float(h));
}

// mma.sync m16n8k16 bf16 (sm_80+; valid on every compile pass — no arch gate needed)
__device__ __forceinline__ void mma16816(float* c, const uint32_t* a, const uint32_t* b) {
    asm volatile(
        "mma.sync.aligned.m16n8k16.row.col.f32.bf16.bf16.f32 "
        "{%0,%1,%2,%3}, {%4,%5,%6,%7}, {%8,%9}, {%0,%1,%2,%3};"
        : "+f"(c[0]), "+f"(c[1]), "+f"(c[2]), "+f"(c[3])
        : "r"(a[0]), "r"(a[1]), "r"(a[2]), "r"(a[3]), "r"(b[0]), "r"(b[1]));
}

// ------------------- W1/W2 -> bf16 hi/lo (one-time) -------------------
__global__ void wcvt(const float* __restrict__ W1, const float* __restrict__ W2) {
    int i = blockIdx.x * 256 + threadIdx.x;
    if (i < Hh * CIN) bf16split(W1[i], g_W1H[i], g_W1L[i]);
    if (i < Hh * Hh)  bf16split(W2[i], g_W2H[i], g_W2L[i]);
}

// ------------------- transpose points2 [B,C2,S] -> g_pts2t [B,S,C2] fp32 --------------
__global__ void transpose_p2(const float* __restrict__ in) {
    __shared__ float tile[32][33];
    int b = blockIdx.z;
    int n0 = blockIdx.x * 32, c0 = blockIdx.y * 32;
    int tx = threadIdx.x, ty = threadIdx.y;
#pragma unroll
    for (int k = 0; k < 4; k++)
        tile[ty + k * 8][tx] = in[((size_t)b * C2c + c0 + ty + k * 8) * Ss + n0 + tx];
    __syncthreads();
#pragma unroll
    for (int k = 0; k < 4; k++) {
        int n = n0 + ty + k * 8;
        g_pts2t[((size_t)b * Ss + n) * C2c + c0 + tx] = tile[tx][ty + k * 8];
    }
}

// ------------------- transpose points1 [B,C1,N] -> g_featH/L rows, cols 0..127 --------
__global__ void transpose_p1(const float* __restrict__ in) {
    __shared__ float tile[32][33];
    int b = blockIdx.z;
    int n0 = blockIdx.x * 32, c0 = blockIdx.y * 32;
    int tx = threadIdx.x, ty = threadIdx.y;
#pragma unroll
    for (int k = 0; k < 4; k++)
        tile[ty + k * 8][tx] = in[((size_t)b * C1c + c0 + ty + k * 8) * Nn + n0 + tx];
    __syncthreads();
#pragma unroll
    for (int k = 0; k < 4; k++) {
        int n = n0 + ty + k * 8;
        size_t o = ((size_t)b * Nn + n) * CIN + c0 + tx;
        bf16split(tile[tx][ty + k * 8], g_featH[o], g_featL[o]);
    }
}

// ------------------- kNN(3) + inverse-distance interpolation (proven core) ----------
__global__ void knn_interp(const float* __restrict__ xyz1, const float* __restrict__ xyz2) {
    __shared__ float4 c4[Ss];
    int b = blockIdx.y;
    int n_base = blockIdx.x * 64;

    const float* x2 = xyz2 + (size_t)b * Ss * 3;
    for (int s = threadIdx.x; s < Ss; s += blockDim.x) {
        float x = x2[s * 3 + 0], y = x2[s * 3 + 1], z = x2[s * 3 + 2];
        c4[s] = make_float4(x, y, z, fmaf(x, x, fmaf(y, y, z * z)));
    }
    __syncthreads();

    int warp = threadIdx.x >> 5, lane = threadIdx.x & 31;
    for (int q = 0; q < 8; q++) {
        int n = n_base + warp * 8 + q;
        const float* xq = xyz1 + ((size_t)b * Nn + n) * 3;
        float qx = xq[0], qy = xq[1], qz = xq[2];
        float qsq = fmaf(qx, qx, fmaf(qy, qy, qz * qz));

        float e0 = 3.4e38f, e1 = 3.4e38f, e2 = 3.4e38f;
        int i0 = 0x7fffffff, i1 = 0x7fffffff, i2 = 0x7fffffff;
#pragma unroll 4
        for (int s = lane; s < Ss; s += 32) {
            float4 c = c4[s];
            float dot = fmaf(qx, c.x, fmaf(qy, c.y, qz * c.z));
            float e = fmaf(-2.0f, dot, c.w);
            if (e < e2) {
                if (e < e1) {
                    e2 = e1; i2 = i1;
                    if (e < e0) { e1 = e0; i1 = i0; e0 = e; i0 = s; }
                    else        { e1 = e;  i1 = s; }
                } else { e2 = e; i2 = s; }
            }
        }
        float be[3]; int bi[3];
        float h = e0; int hi = i0; int slot = 0;
        for (int k = 0; k < 3; k++) {
            float v = h; int vi = hi;
#pragma unroll
            for (int off = 16; off; off >>= 1) {
                float ov = __shfl_xor_sync(0xffffffffu, v, off);
                int   oi = __shfl_xor_sync(0xffffffffu, vi, off);
                if (ov < v || (ov == v && oi < vi)) { v = ov; vi = oi; }
            }
            be[k] = v; bi[k] = vi;
            if (h == v && hi == vi) { slot++; h = (slot == 1) ? e1 : e2; hi = (slot == 1) ? i1 : i2; }
        }
        float d0 = fmaxf(be[0] + qsq, 0.f);
        float d1 = fmaxf(be[1] + qsq, 0.f);
        float d2 = fmaxf(be[2] + qsq, 0.f);
        float r0 = 1.f / (d0 + 1e-8f);
        float r1 = 1.f / (d1 + 1e-8f);
        float r2 = 1.f / (d2 + 1e-8f);
        float inv = 1.f / (r0 + r1 + r2);
        float w0 = r0 * inv, w1 = r1 * inv, w2 = r2 * inv;

        const float* p0 = g_pts2t + ((size_t)b * Ss + bi[0]) * C2c;
        const float* p1 = g_pts2t + ((size_t)b * Ss + bi[1]) * C2c;
        const float* p2 = g_pts2t + ((size_t)b * Ss + bi[2]) * C2c;
        size_t fo = ((size_t)b * Nn + n) * CIN + C1c;
#pragma unroll
        for (int j = 0; j < 8; j++) {
            int c = lane + 32 * j;
            float r = w0 * p0[c] + w1 * p1[c] + w2 * p2[c];
            bf16split(r, g_featH[fo + c], g_featL[fo + c]);
        }
    }
}

// ------------------- GEMM via mma.sync bf16x3: C[P][256] = A[P][K] @ W[256][K]^T ------
// grid (PT, 2), 512 threads. CTA tile 128(M) x 128(N). Warp tile 32x32.
// Weights selected by LAYER *inside* the kernel (device symbols must not cross host ABI).
#define GSM_BYTES 68096
template <int K, int LAYER>
__global__ void __launch_bounds__(512, 1) gemm_mma(const float* __restrict__ bias) {
    extern __shared__ char smc[];
    __nv_bfloat16* sm = (__nv_bfloat16*)smc;
    float* bias_s = (float*)(smc + 67584);

    const __nv_bfloat16* AH = (LAYER == 0) ? g_featH : g_y1H;
    const __nv_bfloat16* AL = (LAYER == 0) ? g_featL : g_y1L;
    const __nv_bfloat16* WH = (LAYER == 0) ? g_W1H : g_W2H;
    const __nv_bfloat16* WL = (LAYER == 0) ? g_W1L : g_W2L;
    float* C = (LAYER == 0) ? g_y1 : g_y2;

    const int tid = threadIdx.x;
    const int p0 = blockIdx.x * 128;
    const int m0 = blockIdx.y * 128;
    const int NS = K / 16;

    if (tid < 128) bias_s[tid] = bias[m0 + tid];

    const int half = tid >> 8;
    const int t8 = tid & 255;
    const int arow = t8 >> 1;
    const int apart = t8 & 1;
    const __nv_bfloat16* Asrc = half ? AL : AH;
    const __nv_bfloat16* Wsrc = half ? WL : WH;
    const int slotA = half;
    const int slotW = 2 + half;

    const int wid = tid >> 5, lane = tid & 31;
    const int wm = wid & 3;
    const int wn = wid >> 2;
    const int gid = lane >> 2, tig = lane & 3;

    float acc[2][4][4];
#pragma unroll
    for (int a = 0; a < 2; a++)
#pragma unroll
        for (int b = 0; b < 4; b++)
#pragma unroll
            for (int c = 0; c < 4; c++) acc[a][b][c] = 0.f;

    {
        uint4 ra = *(const uint4*)&Asrc[(size_t)(p0 + arow) * K + apart * 8];
        uint4 rw = *(const uint4*)&Wsrc[(size_t)(m0 + arow) * K + apart * 8];
        *(uint4*)&sm[slotA * 3072 + arow * 24 + apart * 8] = ra;
        *(uint4*)&sm[slotW * 3072 + arow * 24 + apart * 8] = rw;
    }
    __syncthreads();

    for (int ks = 0; ks < NS; ks++) {
        const int buf = ks & 1;
        const __nv_bfloat16* sAh = sm + buf * 12288;
        const __nv_bfloat16* sAl = sAh + 3072;
        const __nv_bfloat16* sWh = sAh + 6144;
        const __nv_bfloat16* sWl = sAh + 9216;

        uint4 ra, rw;
        const bool nxt = (ks + 1 < NS);
        if (nxt) {
            int k0 = (ks + 1) * 16;
            ra = *(const uint4*)&Asrc[(size_t)(p0 + arow) * K + k0 + apart * 8];
            rw = *(const uint4*)&Wsrc[(size_t)(m0 + arow) * K + k0 + apart * 8];
        }

        uint32_t aH[2][4], aL[2][4], bH[4][2], bL[4][2];
#pragma unroll
        for (int ma = 0; ma < 2; ma++) {
            int r = wm * 32 + ma * 16 + gid;
            aH[ma][0] = *(const uint32_t*)&sAh[r * 24 + tig * 2];
            aH[ma][1] = *(const uint32_t*)&sAh[(r + 8) * 24 + tig * 2];
            aH[ma][2] = *(const uint32_t*)&sAh[r * 24 + tig * 2 + 8];
            aH[ma][3] = *(const uint32_t*)&sAh[(r + 8) * 24 + tig * 2 + 8];
            aL[ma][0] = *(const uint32_t*)&sAl[r * 24 + tig * 2];
            aL[ma][1] = *(const uint32_t*)&sAl[(r + 8) * 24 + tig * 2];
            aL[ma][2] = *(const uint32_t*)&sAl[r * 24 + tig * 2 + 8];
            aL[ma][3] = *(const uint32_t*)&sAl[(r + 8) * 24 + tig * 2 + 8];
        }
#pragma unroll
        for (int na = 0; na < 4; na++) {
            int n = wn * 32 + na * 8 + gid;
            bH[na][0] = *(const uint32_t*)&sWh[n * 24 + tig * 2];
            bH[na][1] = *(const uint32_t*)&sWh[n * 24 + tig * 2 + 8];
            bL[na][0] = *(const uint32_t*)&sWl[n * 24 + tig * 2];
            bL[na][1] = *(const uint32_t*)&sWl[n * 24 + tig * 2 + 8];
        }
#pragma unroll
        for (int ma = 0; ma < 2; ma++)
#pragma unroll
            for (int na = 0; na < 4; na++) {
                mma16816(acc[ma][na], aH[ma], bH[na]);
                mma16816(acc[ma][na], aH[ma], bL[na]);
                mma16816(acc[ma][na], aL[ma], bH[na]);
            }

        __syncthreads();
        if (nxt) {
            int ob = (buf ^ 1) * 12288;
            *(uint4*)&sm[ob + slotA * 3072 + arow * 24 + apart * 8] = ra;
            *(uint4*)&sm[ob + slotW * 3072 + arow * 24 + apart * 8] = rw;
        }
        __syncthreads();
    }

    // ---- epilogue: acc(+bias) -> staging smem -> coalesced out + BN partials ----
    float* stg = (float*)smc;   // [128][132]
#pragma unroll
    for (int ma = 0; ma < 2; ma++)
#pragma unroll
        for (int na = 0; na < 4; na++) {
            int r = wm * 32 + ma * 16 + gid;
            int c = wn * 32 + na * 8 + tig * 2;
            float b0v = bias_s[c], b1v = bias_s[c + 1];
            stg[r * 132 + c]           = acc[ma][na][0] + b0v;
            stg[r * 132 + c + 1]       = acc[ma][na][1] + b1v;
            stg[(r + 8) * 132 + c]     = acc[ma][na][2] + b0v;
            stg[(r + 8) * 132 + c + 1] = acc[ma][na][3] + b1v;
        }
    __syncthreads();
#pragma unroll
    for (int it = 0; it < 8; it++) {
        int idx = tid + it * 512;
        int row = idx >> 5, c4 = idx & 31;
        float4 v = *(const float4*)&stg[row * 132 + c4 * 4];
        *(float4*)&C[(size_t)(p0 + row) * Hh + m0 + c4 * 4] = v;
    }
    if (tid < 128) {
        float s = 0.f, q = 0.f;
#pragma unroll 8
        for (int r = 0; r < 128; r++) {
            float v = stg[r * 132 + tid];
            s += v; q += v * v;
        }
        g_partS[LAYER][m0 + tid][blockIdx.x] = s;
        g_partQ[LAYER][m0 + tid][blockIdx.x] = q;
    }
}

// ------------------- BN stats -> per-channel scale/shift -------------------
template <int LAYER>
__global__ void bnstats(const float* __restrict__ gamma, const float* __restrict__ beta) {
    int m = threadIdx.x;
    float s = 0.f, q = 0.f;
#pragma unroll 8
    for (int i = 0; i < PT; i++) { s += g_partS[LAYER][m][i]; q += g_partQ[LAYER][m][i]; }
    const float invP = 1.f / (float)Pp;
    float mean = s * invP;
    float var = q * invP - mean * mean;
    float sc = gamma[m] * rsqrtf(var + 1e-5f);
    g_scale[LAYER][m] = sc;
    g_shift[LAYER][m] = beta[m] - mean * sc;
}

// ------------------- y1 -> relu(bn1(y1)) -> bf16 hi/lo -------------------
__global__ void bnrelu_cvt() {
    size_t i = ((size_t)blockIdx.x * 256 + threadIdx.x) * 4;
    float4 v = *(const float4*)&g_y1[i];
    int c = (int)(i & (Hh - 1));
    v.x = fmaxf(fmaf(v.x, g_scale[0][c + 0], g_shift[0][c + 0]), 0.f);
    v.y = fmaxf(fmaf(v.y, g_scale[0][c + 1], g_shift[0][c + 1]), 0.f);
    v.z = fmaxf(fmaf(v.z, g_scale[0][c + 2], g_shift[0][c + 2]), 0.f);
    v.w = fmaxf(fmaf(v.w, g_scale[0][c + 3], g_shift[0][c + 3]), 0.f);
    bf16split(v.x, g_y1H[i + 0], g_y1L[i + 0]);
    bf16split(v.y, g_y1H[i + 1], g_y1L[i + 1]);
    bf16split(v.z, g_y1H[i + 2], g_y1L[i + 2]);
    bf16split(v.w, g_y1H[i + 3], g_y1L[i + 3]);
}

// ------------------- final: relu(bn2(y2)) -> out [B][256][N] (transpose) -------------
__global__ void bn_out(float* __restrict__ out) {
    __shared__ float tile[32][33];
    int b = blockIdx.z;
    int n0 = blockIdx.x * 32, m0 = blockIdx.y * 32;
    int tx = threadIdx.x, ty = threadIdx.y;
#pragma unroll
    for (int k = 0; k < 4; k++) {
        int nn = ty + k * 8;
        tile[nn][tx] = g_y2[((size_t)b * Nn + n0 + nn) * Hh + m0 + tx];
    }
    __syncthreads();
#pragma unroll
    for (int k = 0; k < 4; k++) {
        int m = m0 + ty + k * 8;
        float v = fmaxf(fmaf(tile[tx][ty + k * 8], g_scale[1][m], g_shift[1][m]), 0.f);
        out[(size_t)b * Hh * Nn + (size_t)m * Nn + n0 + tx] = v;
    }
}

// ------------------- launch -------------------
extern "C" void kernel_launch(void* const* d_in, const int* in_sizes, int n_in,
                              void* d_out, int out_size) {
    const float* xyz1    = (const float*)d_in[0];
    const float* xyz2    = (const float*)d_in[1];
    const float* points1 = (const float*)d_in[2];
    const float* points2 = (const float*)d_in[3];
    const float* W1      = (const float*)d_in[4];
    const float* b1      = (const float*)d_in[5];
    const float* gamma1  = (const float*)d_in[6];
    const float* beta1   = (const float*)d_in[7];
    const float* W2      = (const float*)d_in[8];
    const float* b2      = (const float*)d_in[9];
    const float* gamma2  = (const float*)d_in[10];
    const float* beta2   = (const float*)d_in[11];
    float* out = (float*)d_out;

    cudaFuncSetAttribute(gemm_mma<CIN, 0>, cudaFuncAttributeMaxDynamicSharedMemorySize, GSM_BYTES);
    cudaFuncSetAttribute(gemm_mma<Hh, 1>,  cudaFuncAttributeMaxDynamicSharedMemorySize, GSM_BYTES);

    dim3 tb(32, 8);
    wcvt<<<(Hh * CIN + 255) / 256, 256>>>(W1, W2);
    transpose_p2<<<dim3(Ss / 32, C2c / 32, Bb), tb>>>(points2);
    transpose_p1<<<dim3(Nn / 32, C1c / 32, Bb), tb>>>(points1);
    knn_interp<<<dim3(Nn / 64, Bb), 256>>>(xyz1, xyz2);
    gemm_mma<CIN, 0><<<dim3(PT, 2), 512, GSM_BYTES>>>(b1);
    bnstats<0><<<1, 256>>>(gamma1, beta1);
    bnrelu_cvt<<<(int)((size_t)Pp * Hh / 1024), 256>>>();
    gemm_mma<Hh, 1><<<dim3(PT, 2), 512, GSM_BYTES>>>(b2);
    bnstats<1><<<1, 256>>>(gamma2, beta2);
    bn_out<<<dim3(Nn / 32, Hh / 32, Bb), tb>>>(out);
    (void)in_sizes; (void)n_in; (void)out_size;
}

// round 10
// speedup vs baseline: 1.2642x; 1.0844x over previous
#include <cuda_runtime.h>
#include <cuda_bf16.h>
#include <cstdint>

#define Bb 4
#define Nn 8192
#define Ss 2048
#define C1c 128
#define C2c 256
#define CIN 384
#define Hh 256
#define Pp (Bb*Nn)      // 32768
#define PT 256          // P tiles of 128

// ------------------- scratch (device globals; no allocation) -------------------
__device__ float g_pts2t[Bb*Ss*C2c];
__device__ float g_feat[(size_t)Pp*CIN];
__device__ float g_y1[(size_t)Pp*Hh];
__device__ float g_y2[(size_t)Pp*Hh];
__device__ __nv_bfloat16 g_W1H[Hh*CIN];
__device__ __nv_bfloat16 g_W1L[Hh*CIN];
__device__ __nv_bfloat16 g_W2H[Hh*Hh];
__device__ __nv_bfloat16 g_W2L[Hh*Hh];
__device__ float g_partS[2][Hh][PT];
__device__ float g_partQ[2][Hh][PT];
__device__ float g_scale[2][Hh];
__device__ float g_shift[2][Hh];

__device__ __forceinline__ void bf16split(float v, __nv_bfloat16& h, __nv_bfloat16& l) {
    h = __float2bfloat16(v);
    l = __float2bfloat16(v - __bfloat162float(h));
}

// mma.sync m16n8k16 bf16 (sm_80+; valid on every compile pass)
__device__ __forceinline__ void mma16816(float* c, const uint32_t* a, const uint32_t* b) {
    asm volatile(
        "mma.sync.aligned.m16n8k16.row.col.f32.bf16.bf16.f32 "
        "{%0,%1,%2,%3}, {%4,%5,%6,%7}, {%8,%9}, {%0,%1,%2,%3};"
        : "+f"(c[0]), "+f"(c[1]), "+f"(c[2]), "+f"(c[3])
        : "r"(a[0]), "r"(a[1]), "r"(a[2]), "r"(a[3]), "r"(b[0]), "r"(b[1]));
}

// ------------------- W1/W2 -> bf16 hi/lo (one-time) -------------------
__global__ void wcvt(const float* __restrict__ W1, const float* __restrict__ W2) {
    int i = blockIdx.x * 256 + threadIdx.x;
    if (i < Hh * CIN) bf16split(W1[i], g_W1H[i], g_W1L[i]);
    if (i < Hh * Hh)  bf16split(W2[i], g_W2H[i], g_W2L[i]);
}

// ------------------- transpose points2 [B,C2,S] -> g_pts2t [B,S,C2] -------------------
__global__ void transpose_p2(const float* __restrict__ in) {
    __shared__ float tile[32][33];
    int b = blockIdx.z;
    int n0 = blockIdx.x * 32, c0 = blockIdx.y * 32;
    int tx = threadIdx.x, ty = threadIdx.y;
#pragma unroll
    for (int k = 0; k < 4; k++)
        tile[ty + k * 8][tx] = in[((size_t)b * C2c + c0 + ty + k * 8) * Ss + n0 + tx];
    __syncthreads();
#pragma unroll
    for (int k = 0; k < 4; k++) {
        int n = n0 + ty + k * 8;
        g_pts2t[((size_t)b * Ss + n) * C2c + c0 + tx] = tile[tx][ty + k * 8];
    }
}

// ------------------- transpose points1 [B,C1,N] -> g_feat cols 0..127 (fp32) ----------
__global__ void transpose_p1(const float* __restrict__ in) {
    __shared__ float tile[32][33];
    int b = blockIdx.z;
    int n0 = blockIdx.x * 32, c0 = blockIdx.y * 32;
    int tx = threadIdx.x, ty = threadIdx.y;
#pragma unroll
    for (int k = 0; k < 4; k++)
        tile[ty + k * 8][tx] = in[((size_t)b * C1c + c0 + ty + k * 8) * Nn + n0 + tx];
    __syncthreads();
#pragma unroll
    for (int k = 0; k < 4; k++) {
        int n = n0 + ty + k * 8;
        g_feat[((size_t)b * Nn + n) * CIN + c0 + tx] = tile[tx][ty + k * 8];
    }
}

// ------------------- kNN(3) + interp, 2 queries per scan (ILP) -------------------
__global__ void knn_interp(const float* __restrict__ xyz1, const float* __restrict__ xyz2) {
    __shared__ float4 c4[Ss];
    int b = blockIdx.y;
    int n_base = blockIdx.x * 64;

    const float* x2 = xyz2 + (size_t)b * Ss * 3;
    for (int s = threadIdx.x; s < Ss; s += blockDim.x) {
        float x = x2[s * 3 + 0], y = x2[s * 3 + 1], z = x2[s * 3 + 2];
        c4[s] = make_float4(x, y, z, fmaf(x, x, fmaf(y, y, z * z)));
    }
    __syncthreads();

    int warp = threadIdx.x >> 5, lane = threadIdx.x & 31;
    for (int qp = 0; qp < 8; qp += 2) {
        int nA = n_base + warp * 8 + qp;
        int nB = nA + 1;
        const float* xa = xyz1 + ((size_t)b * Nn + nA) * 3;
        const float* xb = xyz1 + ((size_t)b * Nn + nB) * 3;
        float ax = xa[0], ay = xa[1], az = xa[2];
        float bx = xb[0], by = xb[1], bz = xb[2];
        float asq = fmaf(ax, ax, fmaf(ay, ay, az * az));
        float bsq = fmaf(bx, bx, fmaf(by, by, bz * bz));

        float Ae0 = 3.4e38f, Ae1 = 3.4e38f, Ae2 = 3.4e38f;
        int   Ai0 = 0x7fffffff, Ai1 = 0x7fffffff, Ai2 = 0x7fffffff;
        float Be0 = 3.4e38f, Be1 = 3.4e38f, Be2 = 3.4e38f;
        int   Bi0 = 0x7fffffff, Bi1 = 0x7fffffff, Bi2 = 0x7fffffff;
#pragma unroll 4
        for (int s = lane; s < Ss; s += 32) {
            float4 c = c4[s];
            float dA = fmaf(ax, c.x, fmaf(ay, c.y, az * c.z));
            float dB = fmaf(bx, c.x, fmaf(by, c.y, bz * c.z));
            float eA = fmaf(-2.0f, dA, c.w);
            float eB = fmaf(-2.0f, dB, c.w);
            if (eA < Ae2) {
                if (eA < Ae1) {
                    Ae2 = Ae1; Ai2 = Ai1;
                    if (eA < Ae0) { Ae1 = Ae0; Ai1 = Ai0; Ae0 = eA; Ai0 = s; }
                    else          { Ae1 = eA;  Ai1 = s; }
                } else { Ae2 = eA; Ai2 = s; }
            }
            if (eB < Be2) {
                if (eB < Be1) {
                    Be2 = Be1; Bi2 = Bi1;
                    if (eB < Be0) { Be1 = Be0; Bi1 = Bi0; Be0 = eB; Bi0 = s; }
                    else          { Be1 = eB;  Bi1 = s; }
                } else { Be2 = eB; Bi2 = s; }
            }
        }

        // merge + gather per query
        for (int which = 0; which < 2; which++) {
            float e0 = which ? Be0 : Ae0, e1 = which ? Be1 : Ae1, e2 = which ? Be2 : Ae2;
            int   i0 = which ? Bi0 : Ai0, i1 = which ? Bi1 : Ai1, i2 = which ? Bi2 : Ai2;
            float qsq = which ? bsq : asq;
            int n = which ? nB : nA;

            float be[3]; int bi[3];
            float h = e0; int hi = i0; int slot = 0;
            for (int k = 0; k < 3; k++) {
                float v = h; int vi = hi;
#pragma unroll
                for (int off = 16; off; off >>= 1) {
                    float ov = __shfl_xor_sync(0xffffffffu, v, off);
                    int   oi = __shfl_xor_sync(0xffffffffu, vi, off);
                    if (ov < v || (ov == v && oi < vi)) { v = ov; vi = oi; }
                }
                be[k] = v; bi[k] = vi;
                if (h == v && hi == vi) { slot++; h = (slot == 1) ? e1 : e2; hi = (slot == 1) ? i1 : i2; }
            }
            float d0 = fmaxf(be[0] + qsq, 0.f);
            float d1 = fmaxf(be[1] + qsq, 0.f);
            float d2 = fmaxf(be[2] + qsq, 0.f);
            float r0 = 1.f / (d0 + 1e-8f);
            float r1 = 1.f / (d1 + 1e-8f);
            float r2 = 1.f / (d2 + 1e-8f);
            float inv = 1.f / (r0 + r1 + r2);
            float w0 = r0 * inv, w1 = r1 * inv, w2 = r2 * inv;

            const float* p0 = g_pts2t + ((size_t)b * Ss + bi[0]) * C2c;
            const float* p1 = g_pts2t + ((size_t)b * Ss + bi[1]) * C2c;
            const float* p2 = g_pts2t + ((size_t)b * Ss + bi[2]) * C2c;
            float* f = g_feat + ((size_t)b * Nn + n) * CIN + C1c;
#pragma unroll
            for (int j = 0; j < 8; j++) {
                int c = lane + 32 * j;
                f[c] = w0 * p0[c] + w1 * p1[c] + w2 * p2[c];
            }
        }
    }
}

// ------------------- GEMM via mma.sync bf16x3 with fused split/BN loader --------------
// A kept fp32 in global; loader does (optional BN+ReLU) + hi/lo split on the fly.
// grid (PT, 2), 512 threads. CTA tile 128(M) x 128(N). Warp tile 32x32.
#define OFF_BIAS  67584
#define OFF_SCALE 68096
#define OFF_SHIFT 69120
#define GSM_BYTES 70144
template <int K, bool APPLY_BN, int LAYER>
__global__ void __launch_bounds__(512, 1) gemm_mma(const float* __restrict__ bias) {
    extern __shared__ char smc[];
    __nv_bfloat16* sm = (__nv_bfloat16*)smc;
    float* bias_s  = (float*)(smc + OFF_BIAS);
    float* scale_s = (float*)(smc + OFF_SCALE);
    float* shift_s = (float*)(smc + OFF_SHIFT);

    const float* A = (LAYER == 0) ? g_feat : g_y1;
    const __nv_bfloat16* WH = (LAYER == 0) ? g_W1H : g_W2H;
    const __nv_bfloat16* WL = (LAYER == 0) ? g_W1L : g_W2L;
    float* C = (LAYER == 0) ? g_y1 : g_y2;

    const int tid = threadIdx.x;
    const int p0 = blockIdx.x * 128;
    const int m0 = blockIdx.y * 128;
    const int NS = K / 16;

    if (tid < 128) bias_s[tid] = bias[m0 + tid];
    if (APPLY_BN && tid < Hh) { scale_s[tid] = g_scale[0][tid]; shift_s[tid] = g_shift[0][tid]; }

    // A loader: thread t -> row t>>2 (0..127), cols (t&3)*4 .. +3 within k-slice
    const int arow = tid >> 2;
    const int acol = (tid & 3) * 4;
    // W loader: threads split hi/lo halves; each loads 8 bf16 (uint4)
    const int half = tid >> 8;
    const int t8 = tid & 255;
    const int wrow = t8 >> 1;
    const int wpart = t8 & 1;
    const __nv_bfloat16* Wsrc = half ? WL : WH;
    const int slotW = 2 + half;    // Wh=2, Wl=3

    const int wid = tid >> 5, lane = tid & 31;
    const int wm = wid & 3;
    const int wn = wid >> 2;
    const int gid = lane >> 2, tig = lane & 3;

    float acc[2][4][4];
#pragma unroll
    for (int a = 0; a < 2; a++)
#pragma unroll
        for (int b = 0; b < 4; b++)
#pragma unroll
            for (int c = 0; c < 4; c++) acc[a][b][c] = 0.f;

    __syncthreads();   // scale_s/bias_s visible before loaders use them

    // convert 4 fp32 -> packed hi (uint2) / lo (uint2)
    auto cvt4 = [&](float4 v, int kcol, uint2& H, uint2& L) {
        if (APPLY_BN) {
            v.x = fmaxf(fmaf(v.x, scale_s[kcol + 0], shift_s[kcol + 0]), 0.f);
            v.y = fmaxf(fmaf(v.y, scale_s[kcol + 1], shift_s[kcol + 1]), 0.f);
            v.z = fmaxf(fmaf(v.z, scale_s[kcol + 2], shift_s[kcol + 2]), 0.f);
            v.w = fmaxf(fmaf(v.w, scale_s[kcol + 3], shift_s[kcol + 3]), 0.f);
        }
        __nv_bfloat16 h0, h1, h2, h3, l0, l1, l2, l3;
        bf16split(v.x, h0, l0); bf16split(v.y, h1, l1);
        bf16split(v.z, h2, l2); bf16split(v.w, h3, l3);
        __nv_bfloat162 hp0 = {h0, h1}, hp1 = {h2, h3}, lp0 = {l0, l1}, lp1 = {l2, l3};
        H = make_uint2(*(uint32_t*)&hp0, *(uint32_t*)&hp1);
        L = make_uint2(*(uint32_t*)&lp0, *(uint32_t*)&lp1);
    };

    // prologue: slice 0 -> buf 0
    {
        float4 va = *(const float4*)&A[(size_t)(p0 + arow) * K + acol];
        uint2 H, L; cvt4(va, acol, H, L);
        *(uint2*)&sm[0 * 3072 + arow * 24 + acol] = H;
        *(uint2*)&sm[1 * 3072 + arow * 24 + acol] = L;
        uint4 rw = *(const uint4*)&Wsrc[(size_t)(m0 + wrow) * K + wpart * 8];
        *(uint4*)&sm[slotW * 3072 + wrow * 24 + wpart * 8] = rw;
    }
    __syncthreads();

    for (int ks = 0; ks < NS; ks++) {
        const int buf = ks & 1;
        const __nv_bfloat16* sAh = sm + buf * 12288;
        const __nv_bfloat16* sAl = sAh + 3072;
        const __nv_bfloat16* sWh = sAh + 6144;
        const __nv_bfloat16* sWl = sAh + 9216;

        uint2 nH, nL; uint4 rw;
        const bool nxt = (ks + 1 < NS);
        if (nxt) {
            int k0 = (ks + 1) * 16;
            float4 va = *(const float4*)&A[(size_t)(p0 + arow) * K + k0 + acol];
            rw = *(const uint4*)&Wsrc[(size_t)(m0 + wrow) * K + k0 + wpart * 8];
            cvt4(va, k0 + acol, nH, nL);
        }

        uint32_t aH[2][4], aL[2][4], bH[4][2], bL[4][2];
#pragma unroll
        for (int ma = 0; ma < 2; ma++) {
            int r = wm * 32 + ma * 16 + gid;
            aH[ma][0] = *(const uint32_t*)&sAh[r * 24 + tig * 2];
            aH[ma][1] = *(const uint32_t*)&sAh[(r + 8) * 24 + tig * 2];
            aH[ma][2] = *(const uint32_t*)&sAh[r * 24 + tig * 2 + 8];
            aH[ma][3] = *(const uint32_t*)&sAh[(r + 8) * 24 + tig * 2 + 8];
            aL[ma][0] = *(const uint32_t*)&sAl[r * 24 + tig * 2];
            aL[ma][1] = *(const uint32_t*)&sAl[(r + 8) * 24 + tig * 2];
            aL[ma][2] = *(const uint32_t*)&sAl[r * 24 + tig * 2 + 8];
            aL[ma][3] = *(const uint32_t*)&sAl[(r + 8) * 24 + tig * 2 + 8];
        }
#pragma unroll
        for (int na = 0; na < 4; na++) {
            int n = wn * 32 + na * 8 + gid;
            bH[na][0] = *(const uint32_t*)&sWh[n * 24 + tig * 2];
            bH[na][1] = *(const uint32_t*)&sWh[n * 24 + tig * 2 + 8];
            bL[na][0] = *(const uint32_t*)&sWl[n * 24 + tig * 2];
            bL[na][1] = *(const uint32_t*)&sWl[n * 24 + tig * 2 + 8];
        }
#pragma unroll
        for (int ma = 0; ma < 2; ma++)
#pragma unroll
            for (int na = 0; na < 4; na++) {
                mma16816(acc[ma][na], aH[ma], bH[na]);
                mma16816(acc[ma][na], aH[ma], bL[na]);
                mma16816(acc[ma][na], aL[ma], bH[na]);
            }

        __syncthreads();
        if (nxt) {
            int ob = (buf ^ 1) * 12288;
            *(uint2*)&sm[ob + 0 * 3072 + arow * 24 + acol] = nH;
            *(uint2*)&sm[ob + 1 * 3072 + arow * 24 + acol] = nL;
            *(uint4*)&sm[ob + slotW * 3072 + wrow * 24 + wpart * 8] = rw;
        }
        __syncthreads();
    }

    // ---- epilogue: acc(+bias) -> staging smem -> coalesced out + BN partials ----
    float* stg = (float*)smc;   // [128][132]
#pragma unroll
    for (int ma = 0; ma < 2; ma++)
#pragma unroll
        for (int na = 0; na < 4; na++) {
            int r = wm * 32 + ma * 16 + gid;
            int c = wn * 32 + na * 8 + tig * 2;
            float b0v = bias_s[c], b1v = bias_s[c + 1];
            stg[r * 132 + c]           = acc[ma][na][0] + b0v;
            stg[r * 132 + c + 1]       = acc[ma][na][1] + b1v;
            stg[(r + 8) * 132 + c]     = acc[ma][na][2] + b0v;
            stg[(r + 8) * 132 + c + 1] = acc[ma][na][3] + b1v;
        }
    __syncthreads();
#pragma unroll
    for (int it = 0; it < 8; it++) {
        int idx = tid + it * 512;
        int row = idx >> 5, c4 = idx & 31;
        float4 v = *(const float4*)&stg[row * 132 + c4 * 4];
        *(float4*)&C[(size_t)(p0 + row) * Hh + m0 + c4 * 4] = v;
    }
    if (tid < 128) {
        float s = 0.f, q = 0.f;
#pragma unroll 8
        for (int r = 0; r < 128; r++) {
            float v = stg[r * 132 + tid];
            s += v; q += v * v;
        }
        g_partS[LAYER][m0 + tid][blockIdx.x] = s;
        g_partQ[LAYER][m0 + tid][blockIdx.x] = q;
    }
}

// ------------------- BN stats -> per-channel scale/shift -------------------
template <int LAYER>
__global__ void bnstats(const float* __restrict__ gamma, const float* __restrict__ beta) {
    int m = threadIdx.x;
    float s = 0.f, q = 0.f;
#pragma unroll 8
    for (int i = 0; i < PT; i++) { s += g_partS[LAYER][m][i]; q += g_partQ[LAYER][m][i]; }
    const float invP = 1.f / (float)Pp;
    float mean = s * invP;
    float var = q * invP - mean * mean;
    float sc = gamma[m] * rsqrtf(var + 1e-5f);
    g_scale[LAYER][m] = sc;
    g_shift[LAYER][m] = beta[m] - mean * sc;
}

// ------------------- final: relu(bn2(y2)) -> out [B][256][N] (transpose) -------------
__global__ void bn_out(float* __restrict__ out) {
    __shared__ float tile[32][33];
    int b = blockIdx.z;
    int n0 = blockIdx.x * 32, m0 = blockIdx.y * 32;
    int tx = threadIdx.x, ty = threadIdx.y;
#pragma unroll
    for (int k = 0; k < 4; k++) {
        int nn = ty + k * 8;
        tile[nn][tx] = g_y2[((size_t)b * Nn + n0 + nn) * Hh + m0 + tx];
    }
    __syncthreads();
#pragma unroll
    for (int k = 0; k < 4; k++) {
        int m = m0 + ty + k * 8;
        float v = fmaxf(fmaf(tile[tx][ty + k * 8], g_scale[1][m], g_shift[1][m]), 0.f);
        out[(size_t)b * Hh * Nn + (size_t)m * Nn + n0 + tx] = v;
    }
}

// ------------------- launch -------------------
extern "C" void kernel_launch(void* const* d_in, const int* in_sizes, int n_in,
                              void* d_out, int out_size) {
    const float* xyz1    = (const float*)d_in[0];
    const float* xyz2    = (const float*)d_in[1];
    const float* points1 = (const float*)d_in[2];
    const float* points2 = (const float*)d_in[3];
    const float* W1      = (const float*)d_in[4];
    const float* b1      = (const float*)d_in[5];
    const float* gamma1  = (const float*)d_in[6];
    const float* beta1   = (const float*)d_in[7];
    const float* W2      = (const float*)d_in[8];
    const float* b2      = (const float*)d_in[9];
    const float* gamma2  = (const float*)d_in[10];
    const float* beta2   = (const float*)d_in[11];
    float* out = (float*)d_out;

    cudaFuncSetAttribute(gemm_mma<CIN, false, 0>, cudaFuncAttributeMaxDynamicSharedMemorySize, GSM_BYTES);
    cudaFuncSetAttribute(gemm_mma<Hh, true, 1>,  cudaFuncAttributeMaxDynamicSharedMemorySize, GSM_BYTES);

    dim3 tb(32, 8);
    wcvt<<<(Hh * CIN + 255) / 256, 256>>>(W1, W2);
    transpose_p2<<<dim3(Ss / 32, C2c / 32, Bb), tb>>>(points2);
    transpose_p1<<<dim3(Nn / 32, C1c / 32, Bb), tb>>>(points1);
    knn_interp<<<dim3(Nn / 64, Bb), 256>>>(xyz1, xyz2);
    gemm_mma<CIN, false, 0><<<dim3(PT, 2), 512, GSM_BYTES>>>(b1);
    bnstats<0><<<1, 256>>>(gamma1, beta1);
    gemm_mma<Hh, true, 1><<<dim3(PT, 2), 512, GSM_BYTES>>>(b2);
    bnstats<1><<<1, 256>>>(gamma2, beta2);
    bn_out<<<dim3(Nn / 32, Hh / 32, Bb), tb>>>(out);
    (void)in_sizes; (void)n_in; (void)out_size;
}

// round 11
// speedup vs baseline: 1.3239x; 1.0472x over previous
#include <cuda_runtime.h>
#include <cuda_bf16.h>
#include <cstdint>

#define Bb 4
#define Nn 8192
#define Ss 2048
#define C1c 128
#define C2c 256
#define CIN 384
#define Hh 256
#define Pp (Bb*Nn)      // 32768
#define PT 256          // P tiles of 128

// ------------------- scratch (device globals; no allocation) -------------------
__device__ float g_pts2t[Bb*Ss*C2c];
__device__ float g_feat[(size_t)Pp*CIN];
__device__ float g_y1[(size_t)Pp*Hh];
__device__ float g_y2[(size_t)Pp*Hh];
__device__ __nv_bfloat16 g_W1H[Hh*CIN];
__device__ __nv_bfloat16 g_W1L[Hh*CIN];
__device__ __nv_bfloat16 g_W2H[Hh*Hh];
__device__ __nv_bfloat16 g_W2L[Hh*Hh];
__device__ float g_partS[2][Hh][PT];
__device__ float g_partQ[2][Hh][PT];
__device__ float g_scale[2][Hh];
__device__ float g_shift[2][Hh];

__device__ __forceinline__ void bf16split(float v, __nv_bfloat16& h, __nv_bfloat16& l) {
    h = __float2bfloat16(v);
    l = __float2bfloat16(v - __bfloat162float(h));
}

// mma.sync m16n8k16 bf16
__device__ __forceinline__ void mma16816(float* c, const uint32_t* a, const uint32_t* b) {
    asm volatile(
        "mma.sync.aligned.m16n8k16.row.col.f32.bf16.bf16.f32 "
        "{%0,%1,%2,%3}, {%4,%5,%6,%7}, {%8,%9}, {%0,%1,%2,%3};"
        : "+f"(c[0]), "+f"(c[1]), "+f"(c[2]), "+f"(c[3])
        : "r"(a[0]), "r"(a[1]), "r"(a[2]), "r"(a[3]), "r"(b[0]), "r"(b[1]));
}

// ------------------- W1/W2 -> bf16 hi/lo (one-time) -------------------
__global__ void wcvt(const float* __restrict__ W1, const float* __restrict__ W2) {
    int i = blockIdx.x * 256 + threadIdx.x;
    if (i < Hh * CIN) bf16split(W1[i], g_W1H[i], g_W1L[i]);
    if (i < Hh * Hh)  bf16split(W2[i], g_W2H[i], g_W2L[i]);
}

// ------------------- transpose points2 [B,C2,S] -> g_pts2t [B,S,C2] -------------------
__global__ void transpose_p2(const float* __restrict__ in) {
    __shared__ float tile[32][33];
    int b = blockIdx.z;
    int n0 = blockIdx.x * 32, c0 = blockIdx.y * 32;
    int tx = threadIdx.x, ty = threadIdx.y;
#pragma unroll
    for (int k = 0; k < 4; k++)
        tile[ty + k * 8][tx] = in[((size_t)b * C2c + c0 + ty + k * 8) * Ss + n0 + tx];
    __syncthreads();
#pragma unroll
    for (int k = 0; k < 4; k++) {
        int n = n0 + ty + k * 8;
        g_pts2t[((size_t)b * Ss + n) * C2c + c0 + tx] = tile[tx][ty + k * 8];
    }
}

// ------------------- transpose points1 [B,C1,N] -> g_feat cols 0..127 (fp32) ----------
__global__ void transpose_p1(const float* __restrict__ in) {
    __shared__ float tile[32][33];
    int b = blockIdx.z;
    int n0 = blockIdx.x * 32, c0 = blockIdx.y * 32;
    int tx = threadIdx.x, ty = threadIdx.y;
#pragma unroll
    for (int k = 0; k < 4; k++)
        tile[ty + k * 8][tx] = in[((size_t)b * C1c + c0 + ty + k * 8) * Nn + n0 + tx];
    __syncthreads();
#pragma unroll
    for (int k = 0; k < 4; k++) {
        int n = n0 + ty + k * 8;
        g_feat[((size_t)b * Nn + n) * CIN + c0 + tx] = tile[tx][ty + k * 8];
    }
}

// ------------------- kNN(3) + interp, 2 queries per scan -------------------
__global__ void knn_interp(const float* __restrict__ xyz1, const float* __restrict__ xyz2) {
    __shared__ float4 c4[Ss];
    int b = blockIdx.y;
    int n_base = blockIdx.x * 64;

    const float* x2 = xyz2 + (size_t)b * Ss * 3;
    for (int s = threadIdx.x; s < Ss; s += blockDim.x) {
        float x = x2[s * 3 + 0], y = x2[s * 3 + 1], z = x2[s * 3 + 2];
        c4[s] = make_float4(x, y, z, fmaf(x, x, fmaf(y, y, z * z)));
    }
    __syncthreads();

    int warp = threadIdx.x >> 5, lane = threadIdx.x & 31;
    for (int qp = 0; qp < 8; qp += 2) {
        int nA = n_base + warp * 8 + qp;
        int nB = nA + 1;
        const float* xa = xyz1 + ((size_t)b * Nn + nA) * 3;
        const float* xb = xyz1 + ((size_t)b * Nn + nB) * 3;
        float ax = xa[0], ay = xa[1], az = xa[2];
        float bx = xb[0], by = xb[1], bz = xb[2];
        float asq = fmaf(ax, ax, fmaf(ay, ay, az * az));
        float bsq = fmaf(bx, bx, fmaf(by, by, bz * bz));

        float Ae0 = 3.4e38f, Ae1 = 3.4e38f, Ae2 = 3.4e38f;
        int   Ai0 = 0x7fffffff, Ai1 = 0x7fffffff, Ai2 = 0x7fffffff;
        float Be0 = 3.4e38f, Be1 = 3.4e38f, Be2 = 3.4e38f;
        int   Bi0 = 0x7fffffff, Bi1 = 0x7fffffff, Bi2 = 0x7fffffff;
#pragma unroll 4
        for (int s = lane; s < Ss; s += 32) {
            float4 c = c4[s];
            float dA = fmaf(ax, c.x, fmaf(ay, c.y, az * c.z));
            float dB = fmaf(bx, c.x, fmaf(by, c.y, bz * c.z));
            float eA = fmaf(-2.0f, dA, c.w);
            float eB = fmaf(-2.0f, dB, c.w);
            if (eA < Ae2) {
                if (eA < Ae1) {
                    Ae2 = Ae1; Ai2 = Ai1;
                    if (eA < Ae0) { Ae1 = Ae0; Ai1 = Ai0; Ae0 = eA; Ai0 = s; }
                    else          { Ae1 = eA;  Ai1 = s; }
                } else { Ae2 = eA; Ai2 = s; }
            }
            if (eB < Be2) {
                if (eB < Be1) {
                    Be2 = Be1; Bi2 = Bi1;
                    if (eB < Be0) { Be1 = Be0; Bi1 = Bi0; Be0 = eB; Bi0 = s; }
                    else          { Be1 = eB;  Bi1 = s; }
                } else { Be2 = eB; Bi2 = s; }
            }
        }

        for (int which = 0; which < 2; which++) {
            float e0 = which ? Be0 : Ae0, e1 = which ? Be1 : Ae1, e2 = which ? Be2 : Ae2;
            int   i0 = which ? Bi0 : Ai0, i1 = which ? Bi1 : Ai1, i2 = which ? Bi2 : Ai2;
            float qsq = which ? bsq : asq;
            int n = which ? nB : nA;

            float be[3]; int bi[3];
            float h = e0; int hi = i0; int slot = 0;
            for (int k = 0; k < 3; k++) {
                float v = h; int vi = hi;
#pragma unroll
                for (int off = 16; off; off >>= 1) {
                    float ov = __shfl_xor_sync(0xffffffffu, v, off);
                    int   oi = __shfl_xor_sync(0xffffffffu, vi, off);
                    if (ov < v || (ov == v && oi < vi)) { v = ov; vi = oi; }
                }
                be[k] = v; bi[k] = vi;
                if (h == v && hi == vi) { slot++; h = (slot == 1) ? e1 : e2; hi = (slot == 1) ? i1 : i2; }
            }
            float d0 = fmaxf(be[0] + qsq, 0.f);
            float d1 = fmaxf(be[1] + qsq, 0.f);
            float d2 = fmaxf(be[2] + qsq, 0.f);
            float r0 = 1.f / (d0 + 1e-8f);
            float r1 = 1.f / (d1 + 1e-8f);
            float r2 = 1.f / (d2 + 1e-8f);
            float inv = 1.f / (r0 + r1 + r2);
            float w0 = r0 * inv, w1 = r1 * inv, w2 = r2 * inv;

            const float* p0 = g_pts2t + ((size_t)b * Ss + bi[0]) * C2c;
            const float* p1 = g_pts2t + ((size_t)b * Ss + bi[1]) * C2c;
            const float* p2 = g_pts2t + ((size_t)b * Ss + bi[2]) * C2c;
            float* f = g_feat + ((size_t)b * Nn + n) * CIN + C1c;
#pragma unroll
            for (int j = 0; j < 8; j++) {
                int c = lane + 32 * j;
                f[c] = w0 * p0[c] + w1 * p1[c] + w2 * p2[c];
            }
        }
    }
}

// ------------------- GEMM via mma.sync bf16x3, k-slice 32, single barrier -------------
// grid (PT, 2), 512 threads. CTA tile 128(M) x 128(N). Warp tile 32x32.
#define SR 40           // smem row stride (bf16 units) — conflict-free frags
#define BUFSZ 20480     // bf16 per buffer: 4 slots x 128 x 40
#define OFF_AH 0
#define OFF_AL 5120
#define OFF_WH 10240
#define OFF_WL 15360
#define OFF_BIAS  81920
#define OFF_SCALE 82432
#define OFF_SHIFT 83456
#define GSM_BYTES 84480
template <int K, bool APPLY_BN, int LAYER>
__global__ void __launch_bounds__(512, 1) gemm_mma(const float* __restrict__ bias) {
    extern __shared__ char smc[];
    __nv_bfloat16* sm = (__nv_bfloat16*)smc;
    float* bias_s  = (float*)(smc + OFF_BIAS);
    float* scale_s = (float*)(smc + OFF_SCALE);
    float* shift_s = (float*)(smc + OFF_SHIFT);

    const float* A = (LAYER == 0) ? g_feat : g_y1;
    const __nv_bfloat16* WH = (LAYER == 0) ? g_W1H : g_W2H;
    const __nv_bfloat16* WL = (LAYER == 0) ? g_W1L : g_W2L;
    float* C = (LAYER == 0) ? g_y1 : g_y2;

    const int tid = threadIdx.x;
    const int p0 = blockIdx.x * 128;
    const int m0 = blockIdx.y * 128;
    const int NS = K / 32;

    if (tid < 128) bias_s[tid] = bias[m0 + tid];
    if (APPLY_BN && tid < Hh) { scale_s[tid] = g_scale[0][tid]; shift_s[tid] = g_shift[0][tid]; }

    // A loader: 2 float4 per thread; idx = tid*2+i -> row=idx>>3, c4=idx&7
    // W loader: 1 uint4 from WH + 1 from WL; wrow=tid>>2, wp=tid&3
    const int wrow = tid >> 2, wp = tid & 3;

    const int wid = tid >> 5, lane = tid & 31;
    const int wm = wid & 3;
    const int wn = wid >> 2;
    const int gid = lane >> 2, tig = lane & 3;

    float acc[2][4][4];
#pragma unroll
    for (int a = 0; a < 2; a++)
#pragma unroll
        for (int b = 0; b < 4; b++)
#pragma unroll
            for (int c = 0; c < 4; c++) acc[a][b][c] = 0.f;

    __syncthreads();   // params visible

    auto cvt4 = [&](float4 v, int kcol, uint2& H, uint2& L) {
        if (APPLY_BN) {
            v.x = fmaxf(fmaf(v.x, scale_s[kcol + 0], shift_s[kcol + 0]), 0.f);
            v.y = fmaxf(fmaf(v.y, scale_s[kcol + 1], shift_s[kcol + 1]), 0.f);
            v.z = fmaxf(fmaf(v.z, scale_s[kcol + 2], shift_s[kcol + 2]), 0.f);
            v.w = fmaxf(fmaf(v.w, scale_s[kcol + 3], shift_s[kcol + 3]), 0.f);
        }
        __nv_bfloat16 h0, h1, h2, h3, l0, l1, l2, l3;
        bf16split(v.x, h0, l0); bf16split(v.y, h1, l1);
        bf16split(v.z, h2, l2); bf16split(v.w, h3, l3);
        __nv_bfloat162 hp0 = {h0, h1}, hp1 = {h2, h3}, lp0 = {l0, l1}, lp1 = {l2, l3};
        H = make_uint2(*(uint32_t*)&hp0, *(uint32_t*)&hp1);
        L = make_uint2(*(uint32_t*)&lp0, *(uint32_t*)&lp1);
    };

    auto store_slice = [&](int kt0, int buf, const float4* pa, uint4 pwh, uint4 pwl) {
        int ob = buf * BUFSZ;
#pragma unroll
        for (int i = 0; i < 2; i++) {
            int idx = tid * 2 + i;
            int row = idx >> 3, c4 = idx & 7;
            uint2 H, L;
            cvt4(pa[i], kt0 + c4 * 4, H, L);
            *(uint2*)&sm[ob + OFF_AH + row * SR + c4 * 4] = H;
            *(uint2*)&sm[ob + OFF_AL + row * SR + c4 * 4] = L;
        }
        *(uint4*)&sm[ob + OFF_WH + wrow * SR + wp * 8] = pwh;
        *(uint4*)&sm[ob + OFF_WL + wrow * SR + wp * 8] = pwl;
    };

    // prologue: slice 0 -> buf 0
    {
        float4 pa[2];
#pragma unroll
        for (int i = 0; i < 2; i++) {
            int idx = tid * 2 + i;
            int row = idx >> 3, c4 = idx & 7;
            pa[i] = *(const float4*)&A[(size_t)(p0 + row) * K + c4 * 4];
        }
        uint4 pwh = *(const uint4*)&WH[(size_t)(m0 + wrow) * K + wp * 8];
        uint4 pwl = *(const uint4*)&WL[(size_t)(m0 + wrow) * K + wp * 8];
        store_slice(0, 0, pa, pwh, pwl);
    }
    __syncthreads();

    for (int ks = 0; ks < NS; ks++) {
        const int buf = ks & 1;
        const __nv_bfloat16* sAh = sm + buf * BUFSZ + OFF_AH;
        const __nv_bfloat16* sAl = sm + buf * BUFSZ + OFF_AL;
        const __nv_bfloat16* sWh = sm + buf * BUFSZ + OFF_WH;
        const __nv_bfloat16* sWl = sm + buf * BUFSZ + OFF_WL;

        float4 pa[2]; uint4 pwh, pwl;
        const bool nxt = (ks + 1 < NS);
        if (nxt) {
            int k0 = (ks + 1) * 32;
#pragma unroll
            for (int i = 0; i < 2; i++) {
                int idx = tid * 2 + i;
                int row = idx >> 3, c4 = idx & 7;
                pa[i] = *(const float4*)&A[(size_t)(p0 + row) * K + k0 + c4 * 4];
            }
            pwh = *(const uint4*)&WH[(size_t)(m0 + wrow) * K + k0 + wp * 8];
            pwl = *(const uint4*)&WL[(size_t)(m0 + wrow) * K + k0 + wp * 8];
        }

#pragma unroll
        for (int kk = 0; kk < 2; kk++) {
            const int co = kk * 16;
            uint32_t aH[2][4], aL[2][4], bH[4][2], bL[4][2];
#pragma unroll
            for (int ma = 0; ma < 2; ma++) {
                int r = wm * 32 + ma * 16 + gid;
                aH[ma][0] = *(const uint32_t*)&sAh[r * SR + co + tig * 2];
                aH[ma][1] = *(const uint32_t*)&sAh[(r + 8) * SR + co + tig * 2];
                aH[ma][2] = *(const uint32_t*)&sAh[r * SR + co + tig * 2 + 8];
                aH[ma][3] = *(const uint32_t*)&sAh[(r + 8) * SR + co + tig * 2 + 8];
                aL[ma][0] = *(const uint32_t*)&sAl[r * SR + co + tig * 2];
                aL[ma][1] = *(const uint32_t*)&sAl[(r + 8) * SR + co + tig * 2];
                aL[ma][2] = *(const uint32_t*)&sAl[r * SR + co + tig * 2 + 8];
                aL[ma][3] = *(const uint32_t*)&sAl[(r + 8) * SR + co + tig * 2 + 8];
            }
#pragma unroll
            for (int na = 0; na < 4; na++) {
                int n = wn * 32 + na * 8 + gid;
                bH[na][0] = *(const uint32_t*)&sWh[n * SR + co + tig * 2];
                bH[na][1] = *(const uint32_t*)&sWh[n * SR + co + tig * 2 + 8];
                bL[na][0] = *(const uint32_t*)&sWl[n * SR + co + tig * 2];
                bL[na][1] = *(const uint32_t*)&sWl[n * SR + co + tig * 2 + 8];
            }
#pragma unroll
            for (int ma = 0; ma < 2; ma++)
#pragma unroll
                for (int na = 0; na < 4; na++) {
                    mma16816(acc[ma][na], aH[ma], bH[na]);
                    mma16816(acc[ma][na], aH[ma], bL[na]);
                    mma16816(acc[ma][na], aL[ma], bH[na]);
                }
        }

        if (nxt) store_slice((ks + 1) * 32, buf ^ 1, pa, pwh, pwl);
        __syncthreads();   // single barrier per slice
    }

    // ---- epilogue: acc(+bias) -> staging smem -> coalesced out + BN partials ----
    float* stg = (float*)smc;   // [128][132] floats (67584B, overlaps tile bufs)
#pragma unroll
    for (int ma = 0; ma < 2; ma++)
#pragma unroll
        for (int na = 0; na < 4; na++) {
            int r = wm * 32 + ma * 16 + gid;
            int c = wn * 32 + na * 8 + tig * 2;
            float b0v = bias_s[c], b1v = bias_s[c + 1];
            stg[r * 132 + c]           = acc[ma][na][0] + b0v;
            stg[r * 132 + c + 1]       = acc[ma][na][1] + b1v;
            stg[(r + 8) * 132 + c]     = acc[ma][na][2] + b0v;
            stg[(r + 8) * 132 + c + 1] = acc[ma][na][3] + b1v;
        }
    __syncthreads();
#pragma unroll
    for (int it = 0; it < 8; it++) {
        int idx = tid + it * 512;
        int row = idx >> 5, c4i = idx & 31;
        float4 v = *(const float4*)&stg[row * 132 + c4i * 4];
        *(float4*)&C[(size_t)(p0 + row) * Hh + m0 + c4i * 4] = v;
    }
    if (tid < 128) {
        float s = 0.f, q = 0.f;
#pragma unroll 8
        for (int r = 0; r < 128; r++) {
            float v = stg[r * 132 + tid];
            s += v; q += v * v;
        }
        g_partS[LAYER][m0 + tid][blockIdx.x] = s;
        g_partQ[LAYER][m0 + tid][blockIdx.x] = q;
    }
}

// ------------------- BN stats -> per-channel scale/shift -------------------
template <int LAYER>
__global__ void bnstats(const float* __restrict__ gamma, const float* __restrict__ beta) {
    int m = threadIdx.x;
    float s = 0.f, q = 0.f;
#pragma unroll 8
    for (int i = 0; i < PT; i++) { s += g_partS[LAYER][m][i]; q += g_partQ[LAYER][m][i]; }
    const float invP = 1.f / (float)Pp;
    float mean = s * invP;
    float var = q * invP - mean * mean;
    float sc = gamma[m] * rsqrtf(var + 1e-5f);
    g_scale[LAYER][m] = sc;
    g_shift[LAYER][m] = beta[m] - mean * sc;
}

// ------------------- final: relu(bn2(y2)) -> out [B][256][N] (transpose) -------------
__global__ void bn_out(float* __restrict__ out) {
    __shared__ float tile[32][33];
    int b = blockIdx.z;
    int n0 = blockIdx.x * 32, m0 = blockIdx.y * 32;
    int tx = threadIdx.x, ty = threadIdx.y;
#pragma unroll
    for (int k = 0; k < 4; k++) {
        int nn = ty + k * 8;
        tile[nn][tx] = g_y2[((size_t)b * Nn + n0 + nn) * Hh + m0 + tx];
    }
    __syncthreads();
#pragma unroll
    for (int k = 0; k < 4; k++) {
        int m = m0 + ty + k * 8;
        float v = fmaxf(fmaf(tile[tx][ty + k * 8], g_scale[1][m], g_shift[1][m]), 0.f);
        out[(size_t)b * Hh * Nn + (size_t)m * Nn + n0 + tx] = v;
    }
}

// ------------------- launch -------------------
extern "C" void kernel_launch(void* const* d_in, const int* in_sizes, int n_in,
                              void* d_out, int out_size) {
    const float* xyz1    = (const float*)d_in[0];
    const float* xyz2    = (const float*)d_in[1];
    const float* points1 = (const float*)d_in[2];
    const float* points2 = (const float*)d_in[3];
    const float* W1      = (const float*)d_in[4];
    const float* b1      = (const float*)d_in[5];
    const float* gamma1  = (const float*)d_in[6];
    const float* beta1   = (const float*)d_in[7];
    const float* W2      = (const float*)d_in[8];
    const float* b2      = (const float*)d_in[9];
    const float* gamma2  = (const float*)d_in[10];
    const float* beta2   = (const float*)d_in[11];
    float* out = (float*)d_out;

    cudaFuncSetAttribute(gemm_mma<CIN, false, 0>, cudaFuncAttributeMaxDynamicSharedMemorySize, GSM_BYTES);
    cudaFuncSetAttribute(gemm_mma<Hh, true, 1>,  cudaFuncAttributeMaxDynamicSharedMemorySize, GSM_BYTES);

    dim3 tb(32, 8);
    wcvt<<<(Hh * CIN + 255) / 256, 256>>>(W1, W2);
    transpose_p2<<<dim3(Ss / 32, C2c / 32, Bb), tb>>>(points2);
    transpose_p1<<<dim3(Nn / 32, C1c / 32, Bb), tb>>>(points1);
    knn_interp<<<dim3(Nn / 64, Bb), 256>>>(xyz1, xyz2);
    gemm_mma<CIN, false, 0><<<dim3(PT, 2), 512, GSM_BYTES>>>(b1);
    bnstats<0><<<1, 256>>>(gamma1, beta1);
    gemm_mma<Hh, true, 1><<<dim3(PT, 2), 512, GSM_BYTES>>>(b2);
    bnstats<1><<<1, 256>>>(gamma2, beta2);
    bn_out<<<dim3(Nn / 32, Hh / 32, Bb), tb>>>(out);
    (void)in_sizes; (void)n_in; (void)out_size;
}